// round 1
// baseline (speedup 1.0000x reference)
#include <cuda_runtime.h>
#include <cstdint>

#define N_NODES 50000
#define N_EDGES 800000
#define EMB     128
#define EDGE_D  64
#define IN_DIM  64
#define OUTD    32

// -------- scratch (static device globals; no allocation) --------
__device__ float g_h0[N_NODES * EMB];
__device__ float g_h1[N_NODES * EMB];
__device__ float g_hm[N_NODES * EMB];
__device__ float g_aggr[N_NODES * EMB];
__device__ float g_hs[N_NODES * EDGE_D];
__device__ float g_hd[N_NODES * EDGE_D];
__device__ float g_ea0[(size_t)N_EDGES * EDGE_D];
__device__ float g_ea1[(size_t)N_EDGES * EDGE_D];
__device__ int   g_src[N_EDGES];
__device__ int   g_dst[N_EDGES];
__device__ float g_epa[N_NODES];
__device__ float g_epb[N_NODES];
__device__ int   g_is64;

// -------- edge_index dtype detection (int64 vs int32) --------
// If int64: int32 view alternates [val, 0, val, 0, ...] since 0 <= idx < 50000.
// If int32: odd words are real indices; 512 consecutive zeros is impossible.
__global__ void detect_idx_kernel(const int* __restrict__ p) {
    __shared__ int any_nz;
    if (threadIdx.x == 0) any_nz = 0;
    __syncthreads();
    for (int i = threadIdx.x; i < 1024; i += blockDim.x) {
        if (p[2 * i + 1] != 0) any_nz = 1;
    }
    __syncthreads();
    if (threadIdx.x == 0) g_is64 = any_nz ? 0 : 1;
}

__global__ void convert_idx_kernel(const void* __restrict__ idx) {
    int i = blockIdx.x * blockDim.x + threadIdx.x;
    if (i >= N_EDGES) return;
    if (g_is64) {
        const long long* p = (const long long*)idx;
        g_src[i] = (int)p[i];
        g_dst[i] = (int)p[N_EDGES + i];
    } else {
        const int* p = (const int*)idx;
        g_src[i] = p[i];
        g_dst[i] = p[N_EDGES + i];
    }
}

__global__ void zero_aggr_kernel() {
    int i = blockIdx.x * blockDim.x + threadIdx.x;
    if (i < N_NODES * EMB / 4)
        ((float4*)g_aggr)[i] = make_float4(0.f, 0.f, 0.f, 0.f);
}

// -------- generic node GEMM: C = act(A1@W[0:K1] + A2@W[K1:K1+K2] + bias) --------
// W is row-major [K1+K2, BN]. K1, K2 must be multiples of BK (holds: 64/128).
template<int BN, int TM, int TN, bool RELU>
__global__ void node_gemm_kernel(const float* __restrict__ A1, int K1,
                                 const float* __restrict__ A2, int K2,
                                 const float* __restrict__ W,
                                 const float* __restrict__ bias,
                                 float* __restrict__ C, int rows) {
    constexpr int BM = 64, BK = 16;
    constexpr int THREADS = (BM / TM) * (BN / TN);
    static_assert(THREADS == 256, "need 256 threads");
    __shared__ float As[BM][BK + 4];
    __shared__ float Ws[BK][BN];
    const int tid = threadIdx.x;
    const int row0 = blockIdx.x * BM;
    const int tc = tid % (BN / TN);
    const int tr = tid / (BN / TN);

    float acc[TM][TN];
#pragma unroll
    for (int i = 0; i < TM; i++)
#pragma unroll
        for (int j = 0; j < TN; j++) acc[i][j] = 0.f;

    const int KT = K1 + K2;
    for (int k0 = 0; k0 < KT; k0 += BK) {
        const float* Asrc; int lda, kl;
        if (k0 < K1) { Asrc = A1; lda = K1; kl = k0; }
        else         { Asrc = A2; lda = K2; kl = k0 - K1; }
        {   // A tile: 64x16, one float4 per thread, transposed-friendly padded layout
            int m = tid >> 2;
            int kq = (tid & 3) * 4;
            float4 v = make_float4(0.f, 0.f, 0.f, 0.f);
            int r = row0 + m;
            if (r < rows) v = *(const float4*)(Asrc + (size_t)r * lda + kl + kq);
            *(float4*)&As[m][kq] = v;
        }
        for (int t = tid; t < BK * BN / 4; t += THREADS) {
            int kk = t / (BN / 4);
            int j = (t % (BN / 4)) * 4;
            *(float4*)&Ws[kk][j] = *(const float4*)(W + (size_t)(k0 + kk) * BN + j);
        }
        __syncthreads();
#pragma unroll
        for (int k = 0; k < BK; k++) {
            float a[TM], w[TN];
#pragma unroll
            for (int i = 0; i < TM; i++) a[i] = As[tr * TM + i][k];
#pragma unroll
            for (int j = 0; j < TN; j++) w[j] = Ws[k][tc * TN + j];
#pragma unroll
            for (int i = 0; i < TM; i++)
#pragma unroll
                for (int j = 0; j < TN; j++)
                    acc[i][j] = fmaf(a[i], w[j], acc[i][j]);
        }
        __syncthreads();
    }

#pragma unroll
    for (int i = 0; i < TM; i++) {
        int r = row0 + tr * TM + i;
        if (r >= rows) continue;
        float buf[TN];
#pragma unroll
        for (int j = 0; j < TN; j++) {
            int col = tc * TN + j;
            float v = acc[i][j];
            if (bias) v += bias[col];
            if (RELU) v = fmaxf(v, 0.f);
            buf[j] = v;
        }
        float* cp = C + (size_t)r * BN + tc * TN;
        if (TN % 4 == 0) {
#pragma unroll
            for (int j = 0; j < TN; j += 4)
                *(float4*)(cp + j) = make_float4(buf[j], buf[j + 1], buf[j + 2], buf[j + 3]);
        } else {  // TN == 2
            *(float2*)cp = make_float2(buf[0], buf[1]);
        }
    }
}

// -------- message + scatter: aggr[dst] += relu(hm[src] + ea@Wm2) --------
__global__ void edge_msg_kernel(const float* __restrict__ EA,   // [E, 64]
                                const float* __restrict__ W,    // [64, 128] (Wm2)
                                const float* __restrict__ HM) { // [N, 128] (h@Wm1 + msg_b)
    constexpr int BM = 64, BN = 128, BK = 16, TM = 4, TN = 8, K = EDGE_D;
    __shared__ float As[BM][BK + 4];
    __shared__ float Ws[BK][BN];
    __shared__ int ssrc[BM], sdst[BM];
    const int tid = threadIdx.x;
    const int row0 = blockIdx.x * BM;
    if (tid < BM) ssrc[tid] = g_src[row0 + tid];
    else if (tid < 2 * BM) sdst[tid - BM] = g_dst[row0 + tid - BM];
    const int tc = tid % (BN / TN);
    const int tr = tid / (BN / TN);

    float acc[TM][TN];
#pragma unroll
    for (int i = 0; i < TM; i++)
#pragma unroll
        for (int j = 0; j < TN; j++) acc[i][j] = 0.f;

    for (int k0 = 0; k0 < K; k0 += BK) {
        {
            int m = tid >> 2;
            int kq = (tid & 3) * 4;
            *(float4*)&As[m][kq] = *(const float4*)(EA + (size_t)(row0 + m) * K + k0 + kq);
        }
        {
            int t = tid;  // BK*BN/4 = 512, 2 per thread
#pragma unroll
            for (int u = 0; u < 2; u++, t += 256) {
                int kk = t / (BN / 4);
                int j = (t % (BN / 4)) * 4;
                *(float4*)&Ws[kk][j] = *(const float4*)(W + (size_t)(k0 + kk) * BN + j);
            }
        }
        __syncthreads();
#pragma unroll
        for (int k = 0; k < BK; k++) {
            float a[TM], w[TN];
#pragma unroll
            for (int i = 0; i < TM; i++) a[i] = As[tr * TM + i][k];
#pragma unroll
            for (int j = 0; j < TN; j++) w[j] = Ws[k][tc * TN + j];
#pragma unroll
            for (int i = 0; i < TM; i++)
#pragma unroll
                for (int j = 0; j < TN; j++)
                    acc[i][j] = fmaf(a[i], w[j], acc[i][j]);
        }
        __syncthreads();
    }

    const int colb = tc * TN;
#pragma unroll
    for (int i = 0; i < TM; i++) {
        int er = tr * TM + i;
        int s = ssrc[er], d = sdst[er];
        const float* hmr = HM + (size_t)s * EMB + colb;
        float4 h0 = *(const float4*)hmr;
        float4 h1 = *(const float4*)(hmr + 4);
        float* ar = g_aggr + (size_t)d * EMB + colb;
        atomicAdd(ar + 0, fmaxf(acc[i][0] + h0.x, 0.f));
        atomicAdd(ar + 1, fmaxf(acc[i][1] + h0.y, 0.f));
        atomicAdd(ar + 2, fmaxf(acc[i][2] + h0.z, 0.f));
        atomicAdd(ar + 3, fmaxf(acc[i][3] + h0.w, 0.f));
        atomicAdd(ar + 4, fmaxf(acc[i][4] + h1.x, 0.f));
        atomicAdd(ar + 5, fmaxf(acc[i][5] + h1.y, 0.f));
        atomicAdd(ar + 6, fmaxf(acc[i][6] + h1.z, 0.f));
        atomicAdd(ar + 7, fmaxf(acc[i][7] + h1.w, 0.f));
    }
}

// -------- edge update: ea' = relu(hs[src] + hd[dst] + ea@We3) --------
__global__ void edge_upd_kernel(const float* __restrict__ EA,   // [E, 64]
                                const float* __restrict__ W,    // [64, 64] (We3)
                                const float* __restrict__ HS,   // [N, 64] (h@We1 + eupd_b)
                                const float* __restrict__ HD,   // [N, 64] (h@We2)
                                float* __restrict__ OUT) {      // [E, 64]
    constexpr int BM = 64, BN = 64, BK = 16, TM = 4, TN = 4, K = EDGE_D;
    __shared__ float As[BM][BK + 4];
    __shared__ float Ws[BK][BN];
    __shared__ int ssrc[BM], sdst[BM];
    const int tid = threadIdx.x;
    const int row0 = blockIdx.x * BM;
    if (tid < BM) ssrc[tid] = g_src[row0 + tid];
    else if (tid < 2 * BM) sdst[tid - BM] = g_dst[row0 + tid - BM];
    const int tc = tid % (BN / TN);
    const int tr = tid / (BN / TN);

    float acc[TM][TN];
#pragma unroll
    for (int i = 0; i < TM; i++)
#pragma unroll
        for (int j = 0; j < TN; j++) acc[i][j] = 0.f;

    for (int k0 = 0; k0 < K; k0 += BK) {
        {
            int m = tid >> 2;
            int kq = (tid & 3) * 4;
            *(float4*)&As[m][kq] = *(const float4*)(EA + (size_t)(row0 + m) * K + k0 + kq);
        }
        {   // BK*BN/4 = 256, 1 per thread
            int kk = tid / (BN / 4);
            int j = (tid % (BN / 4)) * 4;
            *(float4*)&Ws[kk][j] = *(const float4*)(W + (size_t)(k0 + kk) * BN + j);
        }
        __syncthreads();
#pragma unroll
        for (int k = 0; k < BK; k++) {
            float a[TM], w[TN];
#pragma unroll
            for (int i = 0; i < TM; i++) a[i] = As[tr * TM + i][k];
#pragma unroll
            for (int j = 0; j < TN; j++) w[j] = Ws[k][tc * TN + j];
#pragma unroll
            for (int i = 0; i < TM; i++)
#pragma unroll
                for (int j = 0; j < TN; j++)
                    acc[i][j] = fmaf(a[i], w[j], acc[i][j]);
        }
        __syncthreads();
    }

    const int colb = tc * TN;
#pragma unroll
    for (int i = 0; i < TM; i++) {
        int er = tr * TM + i;
        int e = row0 + er;
        int s = ssrc[er], d = sdst[er];
        float4 hs = *(const float4*)(HS + (size_t)s * EDGE_D + colb);
        float4 hd = *(const float4*)(HD + (size_t)d * EDGE_D + colb);
        float4 o;
        o.x = fmaxf(acc[i][0] + hs.x + hd.x, 0.f);
        o.y = fmaxf(acc[i][1] + hs.y + hd.y, 0.f);
        o.z = fmaxf(acc[i][2] + hs.z + hd.z, 0.f);
        o.w = fmaxf(acc[i][3] + hs.w + hd.w, 0.f);
        *(float4*)(OUT + (size_t)e * EDGE_D + colb) = o;
    }
}

// -------- per-node edge_pred precompute: epa = h@ep1 ; epb = h@ep2 + eb --------
__global__ void node_ep_kernel(const float* __restrict__ H,
                               const float* __restrict__ epW,
                               const float* __restrict__ epb) {
    int gt = blockIdx.x * blockDim.x + threadIdx.x;
    int warp = gt >> 5, lane = gt & 31;
    if (warp >= N_NODES) return;
    float4 hv = *(const float4*)(H + (size_t)warp * EMB + lane * 4);
    float4 w1 = *(const float4*)(epW + lane * 4);
    float4 w2 = *(const float4*)(epW + EMB + lane * 4);
    float a = hv.x * w1.x + hv.y * w1.y + hv.z * w1.z + hv.w * w1.w;
    float b = hv.x * w2.x + hv.y * w2.y + hv.z * w2.z + hv.w * w2.w;
#pragma unroll
    for (int off = 16; off; off >>= 1) {
        a += __shfl_xor_sync(0xFFFFFFFFu, a, off);
        b += __shfl_xor_sync(0xFFFFFFFFu, b, off);
    }
    if (lane == 0) { g_epa[warp] = a; g_epb[warp] = b + epb[0]; }
}

// -------- edge_pred: out = ea@ep3 + epa[src] + epb[dst] --------
__global__ void edge_pred_kernel(const float* __restrict__ EA,
                                 const float* __restrict__ epW,
                                 float* __restrict__ OUT) {
    int gt = blockIdx.x * blockDim.x + threadIdx.x;
    int warp = gt >> 5, lane = gt & 31;
    if (warp >= N_EDGES) return;
    float2 ev = *(const float2*)(EA + (size_t)warp * EDGE_D + lane * 2);
    float2 wv = *(const float2*)(epW + 2 * EMB + lane * 2);
    float p = ev.x * wv.x + ev.y * wv.y;
#pragma unroll
    for (int off = 16; off; off >>= 1) p += __shfl_xor_sync(0xFFFFFFFFu, p, off);
    if (lane == 0)
        OUT[warp] = p + g_epa[g_src[warp]] + g_epb[g_dst[warp]];
}

extern "C" void kernel_launch(void* const* d_in, const int* in_sizes, int n_in,
                              void* d_out, int out_size) {
    const float* x         = (const float*)d_in[0];
    const float* edge_attr = (const float*)d_in[1];
    const void*  edge_index= d_in[2];
    const float* emb_W     = (const float*)d_in[3];
    const float* emb_b     = (const float*)d_in[4];
    const float* msg_W     = (const float*)d_in[5];
    const float* msg_b     = (const float*)d_in[6];
    const float* upd_W     = (const float*)d_in[7];
    const float* upd_b     = (const float*)d_in[8];
    const float* eupd_W    = (const float*)d_in[9];
    const float* eupd_b    = (const float*)d_in[10];
    const float* npred_W   = (const float*)d_in[11];
    const float* npred_b   = (const float*)d_in[12];
    const float* epred_W   = (const float*)d_in[13];
    const float* epred_b   = (const float*)d_in[14];

    float* out_node = (float*)d_out;
    float* out_edge = out_node + (size_t)N_NODES * OUTD;

    float *p_h0, *p_h1, *p_hm, *p_aggr, *p_hs, *p_hd, *p_ea0, *p_ea1;
    cudaGetSymbolAddress((void**)&p_h0, g_h0);
    cudaGetSymbolAddress((void**)&p_h1, g_h1);
    cudaGetSymbolAddress((void**)&p_hm, g_hm);
    cudaGetSymbolAddress((void**)&p_aggr, g_aggr);
    cudaGetSymbolAddress((void**)&p_hs, g_hs);
    cudaGetSymbolAddress((void**)&p_hd, g_hd);
    cudaGetSymbolAddress((void**)&p_ea0, g_ea0);
    cudaGetSymbolAddress((void**)&p_ea1, g_ea1);

    const int NODE_BLKS = (N_NODES + 63) / 64;   // 782
    const int EDGE_BLKS = N_EDGES / 64;          // 12500

    detect_idx_kernel<<<1, 256>>>((const int*)edge_index);
    convert_idx_kernel<<<(N_EDGES + 255) / 256, 256>>>(edge_index);

    // embedding: h0 = x @ emb_W + emb_b  (no relu)
    node_gemm_kernel<128, 4, 8, false><<<NODE_BLKS, 256>>>(
        x, IN_DIM, nullptr, 0, emb_W, emb_b, p_h0, N_NODES);

    const float* ea_in = edge_attr;
    float* h_cur = p_h0;
    float* h_nxt = p_h1;

    for (int l = 0; l < 2; l++) {
        const float* mW = msg_W + (size_t)l * (EMB + EDGE_D) * EMB;   // [192,128]
        const float* mb = msg_b + (size_t)l * EMB;
        const float* uW = upd_W + (size_t)l * (2 * EMB) * EMB;        // [256,128]
        const float* ub = upd_b + (size_t)l * EMB;
        const float* eW = eupd_W + (size_t)l * (2 * EMB + EDGE_D) * EDGE_D; // [320,64]
        const float* eb = eupd_b + (size_t)l * EDGE_D;

        // hm = h @ Wm1 + msg_b
        node_gemm_kernel<128, 4, 8, false><<<NODE_BLKS, 256>>>(
            h_cur, EMB, nullptr, 0, mW, mb, p_hm, N_NODES);
        zero_aggr_kernel<<<(N_NODES * EMB / 4 + 255) / 256, 256>>>();
        // aggr[dst] += relu(hm[src] + ea @ Wm2)
        edge_msg_kernel<<<EDGE_BLKS, 256>>>(ea_in, mW + (size_t)EMB * EMB, p_hm);
        // h' = relu(aggr @ Wu1 + h @ Wu2 + ub)
        node_gemm_kernel<128, 4, 8, true><<<NODE_BLKS, 256>>>(
            p_aggr, EMB, h_cur, EMB, uW, ub, h_nxt, N_NODES);
        // hs = h' @ We1 + eb ; hd = h' @ We2
        node_gemm_kernel<64, 4, 4, false><<<NODE_BLKS, 256>>>(
            h_nxt, EMB, nullptr, 0, eW, eb, p_hs, N_NODES);
        node_gemm_kernel<64, 4, 4, false><<<NODE_BLKS, 256>>>(
            h_nxt, EMB, nullptr, 0, eW + (size_t)EMB * EDGE_D, nullptr, p_hd, N_NODES);
        // ea' = relu(hs[src] + hd[dst] + ea @ We3)
        float* ea_out = (l == 0) ? p_ea0 : p_ea1;
        edge_upd_kernel<<<EDGE_BLKS, 256>>>(
            ea_in, eW + (size_t)2 * EMB * EDGE_D, p_hs, p_hd, ea_out);
        ea_in = ea_out;
        float* tmp = h_cur; h_cur = h_nxt; h_nxt = tmp;
    }

    // node_pred = h @ npred_W + npred_b
    node_gemm_kernel<32, 4, 2, false><<<NODE_BLKS, 256>>>(
        h_cur, EMB, nullptr, 0, npred_W, npred_b, out_node, N_NODES);
    // edge_pred = ea@ep3 + (h@ep1)[src] + (h@ep2 + eb)[dst]
    node_ep_kernel<<<(N_NODES * 32 + 255) / 256, 256>>>(h_cur, epred_W, epred_b);
    edge_pred_kernel<<<(N_EDGES * 32 + 255) / 256, 256>>>(ea_in, epred_W, out_edge);
}

// round 2
// speedup vs baseline: 1.5991x; 1.5991x over previous
#include <cuda_runtime.h>
#include <cstdint>

#define N_NODES 50000
#define N_EDGES 800000
#define EMB     128
#define EDGE_D  64
#define IN_DIM  64
#define OUTD    32

// -------- scratch (static device globals; no allocation) --------
__device__ float g_h0[N_NODES * EMB];
__device__ float g_h1[N_NODES * EMB];
__device__ float g_hm[N_NODES * EMB];      // also reused as hsd [N,128]
__device__ float g_aggr[N_NODES * EMB];
__device__ float g_ea0[(size_t)N_EDGES * EDGE_D];
__device__ float g_ea1[(size_t)N_EDGES * EDGE_D];
__device__ int   g_src[N_EDGES];
__device__ int   g_dst[N_EDGES];
__device__ float g_epa[N_NODES];
__device__ float g_epb[N_NODES];
__device__ float g_wpack[128 * 128];
__device__ float g_bpack[128];
__device__ int   g_is64;

__device__ __forceinline__ void red_add_v4(float* p, float a, float b, float c, float d) {
    asm volatile("red.global.add.v4.f32 [%0], {%1,%2,%3,%4};"
                 :: "l"(p), "f"(a), "f"(b), "f"(c), "f"(d) : "memory");
}

// -------- edge_index dtype detection (int64 vs int32) --------
__global__ void detect_idx_kernel(const int* __restrict__ p) {
    __shared__ int any_nz;
    if (threadIdx.x == 0) any_nz = 0;
    __syncthreads();
    for (int i = threadIdx.x; i < 1024; i += blockDim.x)
        if (p[2 * i + 1] != 0) any_nz = 1;
    __syncthreads();
    if (threadIdx.x == 0) g_is64 = any_nz ? 0 : 1;
}

__global__ void convert_idx_kernel(const void* __restrict__ idx) {
    int i = blockIdx.x * blockDim.x + threadIdx.x;
    if (i >= N_EDGES) return;
    if (g_is64) {
        const long long* p = (const long long*)idx;
        g_src[i] = (int)p[i];
        g_dst[i] = (int)p[N_EDGES + i];
    } else {
        const int* p = (const int*)idx;
        g_src[i] = p[i];
        g_dst[i] = p[N_EDGES + i];
    }
}

__global__ void zero_aggr_kernel() {
    int i = blockIdx.x * blockDim.x + threadIdx.x;
    if (i < N_NODES * EMB / 4)
        ((float4*)g_aggr)[i] = make_float4(0.f, 0.f, 0.f, 0.f);
}

// repack eupd weights: W' [128,128] = [We1 | We2]; bias' = [eb | 0]
__global__ void repack_eupd_kernel(const float* __restrict__ eW,
                                   const float* __restrict__ eb) {
    int t = blockIdx.x * blockDim.x + threadIdx.x;
    if (t < 128 * 64) {
        int k = t >> 6, j = t & 63;
        g_wpack[k * 128 + j]      = eW[k * 64 + j];
        g_wpack[k * 128 + 64 + j] = eW[(128 + k) * 64 + j];
    }
    if (t < 64) { g_bpack[t] = eb[t]; g_bpack[64 + t] = 0.f; }
}

// ================= 128x128 SGEMM mainloop (shared structure) =================
// 256 threads, thread tile 8x8 split as rows {tr*4, tr*4+64}, cols {tc*4, tc*4+64}.

#define GEMM128_PROLOG(ldw)                                                     \
    constexpr int BM = 128, BN = 128, BK = 16;                                  \
    __shared__ float As[BK][BM];                                                \
    __shared__ float Bs[BK][BN];                                                \
    const int tid = threadIdx.x;                                                \
    const int row0 = blockIdx.x * BM;                                           \
    const int tr = tid >> 4, tc = tid & 15;                                     \
    const int am0 = tid >> 2, am1 = am0 + 64;                                   \
    const int kq = (tid & 3) * 4;                                               \
    const int bk0 = tid >> 5;                                                   \
    const int bn4 = (tid & 31) * 4;                                             \
    float acc[8][8];                                                            \
    _Pragma("unroll") for (int i = 0; i < 8; i++)                               \
        _Pragma("unroll") for (int j = 0; j < 8; j++) acc[i][j] = 0.f;

#define GEMM128_COMPUTE()                                                       \
    _Pragma("unroll")                                                           \
    for (int k = 0; k < BK; k++) {                                              \
        float4 a0 = *(const float4*)&As[k][tr * 4];                             \
        float4 a1 = *(const float4*)&As[k][tr * 4 + 64];                        \
        float4 b0 = *(const float4*)&Bs[k][tc * 4];                             \
        float4 b1 = *(const float4*)&Bs[k][tc * 4 + 64];                        \
        float a[8] = {a0.x, a0.y, a0.z, a0.w, a1.x, a1.y, a1.z, a1.w};          \
        float b[8] = {b0.x, b0.y, b0.z, b0.w, b1.x, b1.y, b1.z, b1.w};          \
        _Pragma("unroll") for (int i = 0; i < 8; i++)                           \
            _Pragma("unroll") for (int j = 0; j < 8; j++)                       \
                acc[i][j] = fmaf(a[i], b[j], acc[i][j]);                        \
    }

#define GEMM128_STORE_TILE()                                                    \
    As[kq + 0][am0] = pa0.x; As[kq + 1][am0] = pa0.y;                           \
    As[kq + 2][am0] = pa0.z; As[kq + 3][am0] = pa0.w;                           \
    As[kq + 0][am1] = pa1.x; As[kq + 1][am1] = pa1.y;                           \
    As[kq + 2][am1] = pa1.z; As[kq + 3][am1] = pa1.w;                           \
    *(float4*)&Bs[bk0][bn4]     = pb0;                                          \
    *(float4*)&Bs[bk0 + 8][bn4] = pb1;

// -------- node GEMM: C = act(A1@W[0:K1] + A2@W[K1:]+ bias), BN=128 --------
template<bool RELU>
__global__ __launch_bounds__(256) void gemm_node128(
    const float* __restrict__ A1, int K1,
    const float* __restrict__ A2, int K2,
    const float* __restrict__ W,
    const float* __restrict__ bias,
    float* __restrict__ C, int rows)
{
    GEMM128_PROLOG(128)
    const int r0 = min(row0 + am0, rows - 1);
    const int r1 = min(row0 + am1, rows - 1);
    const int nt = (K1 + K2) / BK;

    float4 pa0, pa1, pb0, pb1;
    {
        const float* Asrc = A1; int lda = K1, kl = 0;
        pa0 = *(const float4*)(Asrc + (size_t)r0 * lda + kl + kq);
        pa1 = *(const float4*)(Asrc + (size_t)r1 * lda + kl + kq);
        pb0 = *(const float4*)(W + (size_t)bk0 * BN + bn4);
        pb1 = *(const float4*)(W + (size_t)(bk0 + 8) * BN + bn4);
    }
    for (int kt = 0; kt < nt; kt++) {
        __syncthreads();
        GEMM128_STORE_TILE()
        __syncthreads();
        if (kt + 1 < nt) {
            int k0 = (kt + 1) * BK;
            const float* Asrc; int lda, kl;
            if (k0 < K1) { Asrc = A1; lda = K1; kl = k0; }
            else         { Asrc = A2; lda = K2; kl = k0 - K1; }
            pa0 = *(const float4*)(Asrc + (size_t)r0 * lda + kl + kq);
            pa1 = *(const float4*)(Asrc + (size_t)r1 * lda + kl + kq);
            pb0 = *(const float4*)(W + (size_t)(k0 + bk0) * BN + bn4);
            pb1 = *(const float4*)(W + (size_t)(k0 + bk0 + 8) * BN + bn4);
        }
        GEMM128_COMPUTE()
    }

    float4 bv0 = make_float4(0.f, 0.f, 0.f, 0.f), bv1 = bv0;
    if (bias) {
        bv0 = *(const float4*)(bias + tc * 4);
        bv1 = *(const float4*)(bias + tc * 4 + 64);
    }
#pragma unroll
    for (int g = 0; g < 2; g++) {
#pragma unroll
        for (int i = 0; i < 4; i++) {
            int r = row0 + tr * 4 + g * 64 + i;
            if (r >= rows) continue;
            int ri = g * 4 + i;
            float4 o0, o1;
            o0.x = acc[ri][0] + bv0.x; o0.y = acc[ri][1] + bv0.y;
            o0.z = acc[ri][2] + bv0.z; o0.w = acc[ri][3] + bv0.w;
            o1.x = acc[ri][4] + bv1.x; o1.y = acc[ri][5] + bv1.y;
            o1.z = acc[ri][6] + bv1.z; o1.w = acc[ri][7] + bv1.w;
            if (RELU) {
                o0.x = fmaxf(o0.x, 0.f); o0.y = fmaxf(o0.y, 0.f);
                o0.z = fmaxf(o0.z, 0.f); o0.w = fmaxf(o0.w, 0.f);
                o1.x = fmaxf(o1.x, 0.f); o1.y = fmaxf(o1.y, 0.f);
                o1.z = fmaxf(o1.z, 0.f); o1.w = fmaxf(o1.w, 0.f);
            }
            *(float4*)(C + (size_t)r * BN + tc * 4)      = o0;
            *(float4*)(C + (size_t)r * BN + tc * 4 + 64) = o1;
        }
    }
}

// -------- message + scatter: aggr[dst] += relu(hm[src] + ea@Wm2) --------
__global__ __launch_bounds__(256) void edge_msg_kernel(
    const float* __restrict__ EA,   // [E, 64]
    const float* __restrict__ W,    // [64, 128] (Wm2)
    const float* __restrict__ HM)   // [N, 128]
{
    GEMM128_PROLOG(128)
    __shared__ int ssrc[BM], sdst[BM];
    if (tid < BM) ssrc[tid] = g_src[row0 + tid];
    else          sdst[tid - BM] = g_dst[row0 + tid - BM];
    constexpr int K = EDGE_D, nt = K / BK;  // 4

    float4 pa0, pa1, pb0, pb1;
    pa0 = *(const float4*)(EA + (size_t)(row0 + am0) * K + kq);
    pa1 = *(const float4*)(EA + (size_t)(row0 + am1) * K + kq);
    pb0 = *(const float4*)(W + (size_t)bk0 * BN + bn4);
    pb1 = *(const float4*)(W + (size_t)(bk0 + 8) * BN + bn4);
    for (int kt = 0; kt < nt; kt++) {
        __syncthreads();
        GEMM128_STORE_TILE()
        __syncthreads();
        if (kt + 1 < nt) {
            int k0 = (kt + 1) * BK;
            pa0 = *(const float4*)(EA + (size_t)(row0 + am0) * K + k0 + kq);
            pa1 = *(const float4*)(EA + (size_t)(row0 + am1) * K + k0 + kq);
            pb0 = *(const float4*)(W + (size_t)(k0 + bk0) * BN + bn4);
            pb1 = *(const float4*)(W + (size_t)(k0 + bk0 + 8) * BN + bn4);
        }
        GEMM128_COMPUTE()
    }

#pragma unroll
    for (int g = 0; g < 2; g++) {
#pragma unroll
        for (int i = 0; i < 4; i++) {
            int er = tr * 4 + g * 64 + i;
            int ri = g * 4 + i;
            int s = ssrc[er], d = sdst[er];
            const float* hmr = HM + (size_t)s * EMB;
            float4 h0 = *(const float4*)(hmr + tc * 4);
            float4 h1 = *(const float4*)(hmr + tc * 4 + 64);
            float* ar = g_aggr + (size_t)d * EMB;
            red_add_v4(ar + tc * 4,
                       fmaxf(acc[ri][0] + h0.x, 0.f), fmaxf(acc[ri][1] + h0.y, 0.f),
                       fmaxf(acc[ri][2] + h0.z, 0.f), fmaxf(acc[ri][3] + h0.w, 0.f));
            red_add_v4(ar + tc * 4 + 64,
                       fmaxf(acc[ri][4] + h1.x, 0.f), fmaxf(acc[ri][5] + h1.y, 0.f),
                       fmaxf(acc[ri][6] + h1.z, 0.f), fmaxf(acc[ri][7] + h1.w, 0.f));
        }
    }
}

// -------- edge update: ea' = relu(hsd[src][0:64] + hsd[dst][64:128] + ea@We3) ------
__global__ __launch_bounds__(256) void edge_upd_kernel(
    const float* __restrict__ EA,   // [E, 64]
    const float* __restrict__ W,    // [64, 64] (We3)
    const float* __restrict__ HSD,  // [N, 128] packed [hs | hd]
    float* __restrict__ OUT)        // [E, 64]
{
    constexpr int BM = 128, BN = 64, BK = 16;
    __shared__ float As[BK][BM];
    __shared__ float Bs[BK][BN];
    __shared__ int ssrc[BM], sdst[BM];
    const int tid = threadIdx.x;
    const int row0 = blockIdx.x * BM;
    if (tid < BM) ssrc[tid] = g_src[row0 + tid];
    else          sdst[tid - BM] = g_dst[row0 + tid - BM];
    const int tr = tid >> 4, tc = tid & 15;
    const int am0 = tid >> 2, am1 = am0 + 64;
    const int kq = (tid & 3) * 4;
    const int bk = tid >> 4;          // 0..15
    const int bn4 = (tid & 15) * 4;   // 0..60
    constexpr int K = EDGE_D, nt = K / BK;

    float acc[8][4];
#pragma unroll
    for (int i = 0; i < 8; i++)
#pragma unroll
        for (int j = 0; j < 4; j++) acc[i][j] = 0.f;

    float4 pa0, pa1, pb;
    pa0 = *(const float4*)(EA + (size_t)(row0 + am0) * K + kq);
    pa1 = *(const float4*)(EA + (size_t)(row0 + am1) * K + kq);
    pb  = *(const float4*)(W + (size_t)bk * BN + bn4);
    for (int kt = 0; kt < nt; kt++) {
        __syncthreads();
        As[kq + 0][am0] = pa0.x; As[kq + 1][am0] = pa0.y;
        As[kq + 2][am0] = pa0.z; As[kq + 3][am0] = pa0.w;
        As[kq + 0][am1] = pa1.x; As[kq + 1][am1] = pa1.y;
        As[kq + 2][am1] = pa1.z; As[kq + 3][am1] = pa1.w;
        *(float4*)&Bs[bk][bn4] = pb;
        __syncthreads();
        if (kt + 1 < nt) {
            int k0 = (kt + 1) * BK;
            pa0 = *(const float4*)(EA + (size_t)(row0 + am0) * K + k0 + kq);
            pa1 = *(const float4*)(EA + (size_t)(row0 + am1) * K + k0 + kq);
            pb  = *(const float4*)(W + (size_t)(k0 + bk) * BN + bn4);
        }
#pragma unroll
        for (int k = 0; k < BK; k++) {
            float4 a0 = *(const float4*)&As[k][tr * 4];
            float4 a1 = *(const float4*)&As[k][tr * 4 + 64];
            float4 b0 = *(const float4*)&Bs[k][tc * 4];
            float a[8] = {a0.x, a0.y, a0.z, a0.w, a1.x, a1.y, a1.z, a1.w};
            float b[4] = {b0.x, b0.y, b0.z, b0.w};
#pragma unroll
            for (int i = 0; i < 8; i++)
#pragma unroll
                for (int j = 0; j < 4; j++)
                    acc[i][j] = fmaf(a[i], b[j], acc[i][j]);
        }
    }

#pragma unroll
    for (int g = 0; g < 2; g++) {
#pragma unroll
        for (int i = 0; i < 4; i++) {
            int er = tr * 4 + g * 64 + i;
            int ri = g * 4 + i;
            int e = row0 + er;
            int s = ssrc[er], d = sdst[er];
            float4 hs = *(const float4*)(HSD + (size_t)s * 128 + tc * 4);
            float4 hd = *(const float4*)(HSD + (size_t)d * 128 + 64 + tc * 4);
            float4 o;
            o.x = fmaxf(acc[ri][0] + hs.x + hd.x, 0.f);
            o.y = fmaxf(acc[ri][1] + hs.y + hd.y, 0.f);
            o.z = fmaxf(acc[ri][2] + hs.z + hd.z, 0.f);
            o.w = fmaxf(acc[ri][3] + hs.w + hd.w, 0.f);
            *(float4*)(OUT + (size_t)e * EDGE_D + tc * 4) = o;
        }
    }
}

// -------- small node GEMM for npred (BN=32) --------
template<int BN, int TM, int TN, bool RELU>
__global__ void node_gemm_small(const float* __restrict__ A1, int K1,
                                const float* __restrict__ W,
                                const float* __restrict__ bias,
                                float* __restrict__ C, int rows) {
    constexpr int BM = 64, BK = 16;
    constexpr int THREADS = (BM / TM) * (BN / TN);
    __shared__ float As[BM][BK + 4];
    __shared__ float Ws[BK][BN];
    const int tid = threadIdx.x;
    const int row0 = blockIdx.x * BM;
    const int tc = tid % (BN / TN);
    const int tr = tid / (BN / TN);
    float acc[TM][TN];
#pragma unroll
    for (int i = 0; i < TM; i++)
#pragma unroll
        for (int j = 0; j < TN; j++) acc[i][j] = 0.f;
    for (int k0 = 0; k0 < K1; k0 += BK) {
        {
            int m = tid >> 2;
            int kqq = (tid & 3) * 4;
            float4 v = make_float4(0.f, 0.f, 0.f, 0.f);
            int r = row0 + m;
            if (r < rows) v = *(const float4*)(A1 + (size_t)r * K1 + k0 + kqq);
            *(float4*)&As[m][kqq] = v;
        }
        for (int t = tid; t < BK * BN / 4; t += THREADS) {
            int kk = t / (BN / 4);
            int j = (t % (BN / 4)) * 4;
            *(float4*)&Ws[kk][j] = *(const float4*)(W + (size_t)(k0 + kk) * BN + j);
        }
        __syncthreads();
#pragma unroll
        for (int k = 0; k < BK; k++) {
            float a[TM], w[TN];
#pragma unroll
            for (int i = 0; i < TM; i++) a[i] = As[tr * TM + i][k];
#pragma unroll
            for (int j = 0; j < TN; j++) w[j] = Ws[k][tc * TN + j];
#pragma unroll
            for (int i = 0; i < TM; i++)
#pragma unroll
                for (int j = 0; j < TN; j++)
                    acc[i][j] = fmaf(a[i], w[j], acc[i][j]);
        }
        __syncthreads();
    }
#pragma unroll
    for (int i = 0; i < TM; i++) {
        int r = row0 + tr * TM + i;
        if (r >= rows) continue;
#pragma unroll
        for (int j = 0; j < TN; j++) {
            int col = tc * TN + j;
            float v = acc[i][j] + (bias ? bias[col] : 0.f);
            if (RELU) v = fmaxf(v, 0.f);
            C[(size_t)r * BN + col] = v;
        }
    }
}

// -------- per-node edge_pred precompute --------
__global__ void node_ep_kernel(const float* __restrict__ H,
                               const float* __restrict__ epW,
                               const float* __restrict__ epb) {
    int gt = blockIdx.x * blockDim.x + threadIdx.x;
    int warp = gt >> 5, lane = gt & 31;
    if (warp >= N_NODES) return;
    float4 hv = *(const float4*)(H + (size_t)warp * EMB + lane * 4);
    float4 w1 = *(const float4*)(epW + lane * 4);
    float4 w2 = *(const float4*)(epW + EMB + lane * 4);
    float a = hv.x * w1.x + hv.y * w1.y + hv.z * w1.z + hv.w * w1.w;
    float b = hv.x * w2.x + hv.y * w2.y + hv.z * w2.z + hv.w * w2.w;
#pragma unroll
    for (int off = 16; off; off >>= 1) {
        a += __shfl_xor_sync(0xFFFFFFFFu, a, off);
        b += __shfl_xor_sync(0xFFFFFFFFu, b, off);
    }
    if (lane == 0) { g_epa[warp] = a; g_epb[warp] = b + epb[0]; }
}

// -------- edge_pred --------
__global__ void edge_pred_kernel(const float* __restrict__ EA,
                                 const float* __restrict__ epW,
                                 float* __restrict__ OUT) {
    int gt = blockIdx.x * blockDim.x + threadIdx.x;
    int warp = gt >> 5, lane = gt & 31;
    if (warp >= N_EDGES) return;
    float2 ev = *(const float2*)(EA + (size_t)warp * EDGE_D + lane * 2);
    float2 wv = *(const float2*)(epW + 2 * EMB + lane * 2);
    float p = ev.x * wv.x + ev.y * wv.y;
#pragma unroll
    for (int off = 16; off; off >>= 1) p += __shfl_xor_sync(0xFFFFFFFFu, p, off);
    if (lane == 0)
        OUT[warp] = p + g_epa[g_src[warp]] + g_epb[g_dst[warp]];
}

extern "C" void kernel_launch(void* const* d_in, const int* in_sizes, int n_in,
                              void* d_out, int out_size) {
    const float* x         = (const float*)d_in[0];
    const float* edge_attr = (const float*)d_in[1];
    const void*  edge_index= d_in[2];
    const float* emb_W     = (const float*)d_in[3];
    const float* emb_b     = (const float*)d_in[4];
    const float* msg_W     = (const float*)d_in[5];
    const float* msg_b     = (const float*)d_in[6];
    const float* upd_W     = (const float*)d_in[7];
    const float* upd_b     = (const float*)d_in[8];
    const float* eupd_W    = (const float*)d_in[9];
    const float* eupd_b    = (const float*)d_in[10];
    const float* npred_W   = (const float*)d_in[11];
    const float* npred_b   = (const float*)d_in[12];
    const float* epred_W   = (const float*)d_in[13];
    const float* epred_b   = (const float*)d_in[14];

    float* out_node = (float*)d_out;
    float* out_edge = out_node + (size_t)N_NODES * OUTD;

    float *p_h0, *p_h1, *p_hm, *p_aggr, *p_ea0, *p_ea1, *p_wpack, *p_bpack;
    cudaGetSymbolAddress((void**)&p_h0, g_h0);
    cudaGetSymbolAddress((void**)&p_h1, g_h1);
    cudaGetSymbolAddress((void**)&p_hm, g_hm);
    cudaGetSymbolAddress((void**)&p_aggr, g_aggr);
    cudaGetSymbolAddress((void**)&p_ea0, g_ea0);
    cudaGetSymbolAddress((void**)&p_ea1, g_ea1);
    cudaGetSymbolAddress((void**)&p_wpack, g_wpack);
    cudaGetSymbolAddress((void**)&p_bpack, g_bpack);

    const int NODE_BLKS = (N_NODES + 127) / 128;  // 391
    const int EDGE_BLKS = N_EDGES / 128;          // 6250

    detect_idx_kernel<<<1, 256>>>((const int*)edge_index);
    convert_idx_kernel<<<(N_EDGES + 255) / 256, 256>>>(edge_index);

    // embedding: h0 = x @ emb_W + emb_b
    gemm_node128<false><<<NODE_BLKS, 256>>>(x, IN_DIM, nullptr, 0,
                                            emb_W, emb_b, p_h0, N_NODES);

    const float* ea_in = edge_attr;
    float* h_cur = p_h0;
    float* h_nxt = p_h1;

    for (int l = 0; l < 2; l++) {
        const float* mW = msg_W + (size_t)l * (EMB + EDGE_D) * EMB;
        const float* mb = msg_b + (size_t)l * EMB;
        const float* uW = upd_W + (size_t)l * (2 * EMB) * EMB;
        const float* ub = upd_b + (size_t)l * EMB;
        const float* eW = eupd_W + (size_t)l * (2 * EMB + EDGE_D) * EDGE_D;
        const float* eb = eupd_b + (size_t)l * EDGE_D;

        // hm = h @ Wm1 + msg_b
        gemm_node128<false><<<NODE_BLKS, 256>>>(h_cur, EMB, nullptr, 0,
                                                mW, mb, p_hm, N_NODES);
        zero_aggr_kernel<<<(N_NODES * EMB / 4 + 255) / 256, 256>>>();
        // aggr[dst] += relu(hm[src] + ea @ Wm2)
        edge_msg_kernel<<<EDGE_BLKS, 256>>>(ea_in, mW + (size_t)EMB * EMB, p_hm);
        // h' = relu(aggr @ Wu1 + h @ Wu2 + ub)
        gemm_node128<true><<<NODE_BLKS, 256>>>(p_aggr, EMB, h_cur, EMB,
                                               uW, ub, h_nxt, N_NODES);
        // hsd = h' @ [We1|We2] + [eb|0]   (reuse hm buffer)
        repack_eupd_kernel<<<32, 256>>>(eW, eb);
        gemm_node128<false><<<NODE_BLKS, 256>>>(h_nxt, EMB, nullptr, 0,
                                                p_wpack, p_bpack, p_hm, N_NODES);
        // ea' = relu(hsd[src][0:64] + hsd[dst][64:128] + ea @ We3)
        float* ea_out = (l == 0) ? p_ea0 : p_ea1;
        edge_upd_kernel<<<EDGE_BLKS, 256>>>(ea_in, eW + (size_t)2 * EMB * EDGE_D,
                                            p_hm, ea_out);
        ea_in = ea_out;
        float* tmp = h_cur; h_cur = h_nxt; h_nxt = tmp;
    }

    // node_pred = h @ npred_W + npred_b
    node_gemm_small<32, 4, 2, false><<<(N_NODES + 63) / 64, 256>>>(
        h_cur, EMB, npred_W, npred_b, out_node, N_NODES);
    // edge_pred
    node_ep_kernel<<<(N_NODES * 32 + 255) / 256, 256>>>(h_cur, epred_W, epred_b);
    edge_pred_kernel<<<(N_EDGES * 32 + 255) / 256, 256>>>(ea_in, epred_W, out_edge);
}